// round 1
// baseline (speedup 1.0000x reference)
#include <cuda_runtime.h>

// ---------------------------------------------------------------------------
// pLoss: pot = S f^T ; P = softmax_s(pot) ; pMargin = P^T S ; masked BCE loss.
//
// Single-pass softmax trick: S is binary => pot[s,b] <= U_b = sum_i max(f,0).
// Use U_b as the shift: w = exp(pot - U), Z = sum w, M = sum w*S,
// pMargin = M / Z. Identical to max-shifted softmax (common scale cancels),
// fp32-safe (w <= 1, underflow only for contributions < e^-78 relative).
//
// Kernels:
//  1) prep:     U_b
//  2) main:     grid (74 splits x 4 batch-tiles of 128), per block:
//               chunked s-loop (64 states/chunk):
//                 phase1: pot tile via register-tiled GEMM (smem f^T, S^T)
//                 exp -> w to smem, Z partials
//                 phase2: M[b,i] += w[s,b]*S[s,i] register-tiled
//               writes per-split slabs (deterministic, no global fp atomics)
//  3) zred:     Z[b] = sum over splits
//  4) finalize: pMargin -> out[1..], per-element BCE, block partial sums
//  5) loss:     out[0] = sum(partials)/512
// ---------------------------------------------------------------------------

#define NSTATES 32768
#define NB      512
#define NL      64
#define SPLITS  74
#define SPS     443          // ceil(32768/74); last split clipped
#define BT      128          // batch tile
#define BTILES  4
#define SC      64           // state chunk
#define THREADS 256

#define SF_STR  136          // f^T row stride (pad: 16B-aligned rows, bank spread)
#define ST_STR  68           // S^T row stride
#define WB_STR  132          // w row stride
#define SMEM_FLOATS (64*SF_STR + 64*ST_STR + 64*WB_STR + 128)
#define SMEM_BYTES  (SMEM_FLOATS * 4)

__device__ float g_U[NB];
__device__ float g_Zpart[SPLITS * NB];
__device__ float g_Z[NB];
__device__ float g_Mpart[SPLITS * NB * NL];
__device__ float g_lpart[128];

__global__ void prep_kernel(const float* __restrict__ f) {
    int b = threadIdx.x;
    const float* fr = f + b * NL;
    float u = 0.f;
    #pragma unroll
    for (int i = 0; i < NL; i++) u += fmaxf(fr[i], 0.f);
    g_U[b] = u;
}

__global__ __launch_bounds__(THREADS, 2)
void main_kernel(const float* __restrict__ f, const float* __restrict__ S) {
    extern __shared__ float sm[];
    float* sf   = sm;                      // [64][SF_STR]  f^T : sf[i][b_local]
    float* sT   = sm + 64 * SF_STR;        // [64][ST_STR]  S^T : sT[i][s_local]
    float* wb   = sT + 64 * ST_STR;        // [64][WB_STR]  w   : wb[s_local][b_local]
    float* Zloc = wb + 64 * WB_STR;        // [128]

    const int tid     = threadIdx.x;
    const int b0      = blockIdx.y * BT;
    const int s_begin = blockIdx.x * SPS;
    const int s_end   = min(NSTATES, s_begin + SPS);

    // load f tile transposed into smem
    for (int e = tid; e < BT * NL; e += THREADS) {
        int bl = e >> 6, i = e & 63;
        sf[i * SF_STR + bl] = f[(b0 + bl) * NL + i];
    }
    if (tid < BT) Zloc[tid] = 0.f;

    // phase-1 mapping: 16 b-groups (8 b each) x 16 s-groups (4 s each)
    const int bgrp1 = tid & 15;
    const int sgrp1 = tid >> 4;
    // phase-2 mapping: 32 b-groups (4 b each) x 8 i-groups (8 i each)
    const int bgrp2 = tid & 31;
    const int igrp2 = tid >> 5;

    float U8[8];
    #pragma unroll
    for (int j = 0; j < 8; j++) U8[j] = g_U[b0 + bgrp1 * 8 + j];

    float acc[4][8];
    #pragma unroll
    for (int bb = 0; bb < 4; bb++)
        #pragma unroll
        for (int k = 0; k < 8; k++) acc[bb][k] = 0.f;
    float zacc[8];
    #pragma unroll
    for (int j = 0; j < 8; j++) zacc[j] = 0.f;

    for (int sc = s_begin; sc < s_end; sc += SC) {
        // load S chunk transposed (zero-pad past s_end)
        for (int e = tid; e < SC * NL; e += THREADS) {
            int sl = e >> 6, i = e & 63;
            int s = sc + sl;
            sT[i * ST_STR + sl] = (s < s_end) ? S[s * NL + i] : 0.f;
        }
        __syncthreads();

        // ---- phase 1: pot[4 s][8 b] = sum_i S[s,i] * f[b,i] ----
        float pot[4][8];
        #pragma unroll
        for (int si = 0; si < 4; si++)
            #pragma unroll
            for (int j = 0; j < 8; j++) pot[si][j] = 0.f;

        #pragma unroll 8
        for (int i = 0; i < 64; i++) {
            const float4 av = *(const float4*)(sT + i * ST_STR + (sgrp1 << 2));
            const float4 c0 = *(const float4*)(sf + i * SF_STR + (bgrp1 << 3));
            const float4 c1 = *(const float4*)(sf + i * SF_STR + (bgrp1 << 3) + 4);
            float as[4] = {av.x, av.y, av.z, av.w};
            float cs[8] = {c0.x, c0.y, c0.z, c0.w, c1.x, c1.y, c1.z, c1.w};
            #pragma unroll
            for (int si = 0; si < 4; si++)
                #pragma unroll
                for (int j = 0; j < 8; j++)
                    pot[si][j] = fmaf(as[si], cs[j], pot[si][j]);
        }

        // ---- exp, Z partials, w to smem ----
        #pragma unroll
        for (int si = 0; si < 4; si++) {
            int s = sc + (sgrp1 << 2) + si;
            float wv[8];
            if (s < s_end) {
                #pragma unroll
                for (int j = 0; j < 8; j++) {
                    wv[j] = __expf(pot[si][j] - U8[j]);
                    zacc[j] += wv[j];
                }
            } else {
                #pragma unroll
                for (int j = 0; j < 8; j++) wv[j] = 0.f;
            }
            float4* dst = (float4*)(wb + ((sgrp1 << 2) + si) * WB_STR + (bgrp1 << 3));
            dst[0] = make_float4(wv[0], wv[1], wv[2], wv[3]);
            dst[1] = make_float4(wv[4], wv[5], wv[6], wv[7]);
        }
        __syncthreads();

        // ---- phase 2: acc[b][i] += w[s,b] * S[s,i] ----
        #pragma unroll 4
        for (int sl = 0; sl < SC; sl++) {
            const float4 wv = *(const float4*)(wb + sl * WB_STR + (bgrp2 << 2));
            #pragma unroll
            for (int k = 0; k < 8; k++) {
                float sv = sT[(igrp2 * 8 + k) * ST_STR + sl];
                acc[0][k] = fmaf(wv.x, sv, acc[0][k]);
                acc[1][k] = fmaf(wv.y, sv, acc[1][k]);
                acc[2][k] = fmaf(wv.z, sv, acc[2][k]);
                acc[3][k] = fmaf(wv.w, sv, acc[3][k]);
            }
        }
        __syncthreads();
    }

    // ---- Z partials to global (smem atomics only, once per block) ----
    #pragma unroll
    for (int j = 0; j < 8; j++) atomicAdd(&Zloc[(bgrp1 << 3) + j], zacc[j]);
    __syncthreads();
    if (tid < BT) g_Zpart[blockIdx.x * NB + b0 + tid] = Zloc[tid];

    // ---- M partials to per-split slab ----
    float* mdst = g_Mpart + blockIdx.x * (NB * NL);
    #pragma unroll
    for (int bb = 0; bb < 4; bb++) {
        int b = b0 + (bgrp2 << 2) + bb;
        float4* p = (float4*)(mdst + b * NL + igrp2 * 8);
        p[0] = make_float4(acc[bb][0], acc[bb][1], acc[bb][2], acc[bb][3]);
        p[1] = make_float4(acc[bb][4], acc[bb][5], acc[bb][6], acc[bb][7]);
    }
}

__global__ void zred_kernel() {
    int b = threadIdx.x;  // 512 threads
    float z = 0.f;
    #pragma unroll 2
    for (int k = 0; k < SPLITS; k++) z += g_Zpart[k * NB + b];
    g_Z[b] = z;
}

__global__ void finalize_kernel(const float* __restrict__ y,
                                const float* __restrict__ mask,
                                float* __restrict__ out) {
    int idx = blockIdx.x * 256 + threadIdx.x;  // 0..32767
    float m = 0.f;
    #pragma unroll 2
    for (int k = 0; k < SPLITS; k++) m += g_Mpart[k * (NB * NL) + idx];
    float p = m / g_Z[idx >> 6];
    out[1 + idx] = p;

    float yv = y[idx], mv = mask[idx];
    float lp  = fmaxf(logf(p), -100.f);                       // log(0)->-inf->-100
    float l1p = fmaxf(logf(fmaxf(1.f - p, 0.f)), -100.f);
    float bce = -(yv * lp + (1.f - yv) * l1p) * mv;

    __shared__ float red[256];
    red[threadIdx.x] = bce;
    __syncthreads();
    #pragma unroll
    for (int off = 128; off > 0; off >>= 1) {
        if (threadIdx.x < off) red[threadIdx.x] += red[threadIdx.x + off];
        __syncthreads();
    }
    if (threadIdx.x == 0) g_lpart[blockIdx.x] = red[0];
}

__global__ void loss_kernel(float* __restrict__ out) {
    __shared__ float red[128];
    red[threadIdx.x] = g_lpart[threadIdx.x];
    __syncthreads();
    #pragma unroll
    for (int off = 64; off > 0; off >>= 1) {
        if (threadIdx.x < off) red[threadIdx.x] += red[threadIdx.x + off];
        __syncthreads();
    }
    if (threadIdx.x == 0) out[0] = red[0] * (1.f / NB);
}

extern "C" void kernel_launch(void* const* d_in, const int* in_sizes, int n_in,
                              void* d_out, int out_size) {
    const float* f    = (const float*)d_in[0];
    const float* S    = (const float*)d_in[1];
    const float* y    = (const float*)d_in[2];
    const float* mask = (const float*)d_in[3];
    float* out = (float*)d_out;

    cudaFuncSetAttribute(main_kernel, cudaFuncAttributeMaxDynamicSharedMemorySize,
                         SMEM_BYTES);

    prep_kernel<<<1, NB>>>(f);
    dim3 grid(SPLITS, BTILES);
    main_kernel<<<grid, THREADS, SMEM_BYTES>>>(f, S);
    zred_kernel<<<1, NB>>>();
    finalize_kernel<<<NB * NL / 256, 256>>>(y, mask, out);
    loss_kernel<<<1, 128>>>(out);
}

// round 3
// speedup vs baseline: 4.3668x; 4.3668x over previous
#include <cuda_runtime.h>

// ---------------------------------------------------------------------------
// pLoss via mma.sync (bf16 HMMA): pot = S f^T ; P = softmax_s ; pMargin = P^T S.
// Single-pass softmax with U_b = sum_i max(f,0) shift (S binary => pot <= U).
// f and w are exact hi/lo bf16 splits; S is {0,1} (exact bf16).
// 148 CTAs (37 state-splits x 4 batch-tiles of 128), 512 full chunks of 64.
// w A-fragments for GEMM2 are repacked in-register from GEMM1 D-fragments.
// ---------------------------------------------------------------------------

#define NB       512
#define NL       64
#define SPLITS   37
#define CPS      14          // chunks per split (last split: 8)
#define TOTCH    512         // 512 * 64 = 32768 states exactly

// SMEM (bytes): 4 S tile buffers (ss0,st0,ss1,st1), each 64 rows x 144B
#define SSOF(b)  ((b) * 18432)
#define STOF(b)  ((b) * 18432 + 9216)
#define ZOFF     36864       // Upart[2][128] floats
#define SMEM_BYTES (36864 + 1024)
// f staging (overlaps buffers, pre-loop only): 128 rows x 272B = 34816 <= 36864

__device__ float g_Zpart[SPLITS * NB];
__device__ float g_Mpart[SPLITS * NB * NL];
__device__ float g_lpart[256];

// ---------------- helpers ----------------
__device__ __forceinline__ unsigned smem_u32(const void* p) {
    unsigned a;
    asm("{ .reg .u64 t; cvta.to.shared.u64 t, %1; cvt.u32.u64 %0, t; }"
        : "=r"(a) : "l"(p));
    return a;
}
__device__ __forceinline__ void ldsm4(unsigned* r, unsigned addr) {
    asm volatile("ldmatrix.sync.aligned.m8n8.x4.shared.b16 {%0,%1,%2,%3}, [%4];"
                 : "=r"(r[0]), "=r"(r[1]), "=r"(r[2]), "=r"(r[3]) : "r"(addr));
}
__device__ __forceinline__ void mma16816(float* d, const unsigned* a,
                                         unsigned b0, unsigned b1) {
    asm volatile(
        "mma.sync.aligned.m16n8k16.row.col.f32.bf16.bf16.f32 "
        "{%0,%1,%2,%3}, {%4,%5,%6,%7}, {%8,%9}, {%0,%1,%2,%3};"
        : "+f"(d[0]), "+f"(d[1]), "+f"(d[2]), "+f"(d[3])
        : "r"(a[0]), "r"(a[1]), "r"(a[2]), "r"(a[3]), "r"(b0), "r"(b1));
}
__device__ __forceinline__ unsigned packhi(float a, float b) {
    return __byte_perm(__float_as_uint(a), __float_as_uint(b), 0x7632);
}
__device__ __forceinline__ unsigned packlo(float a, float b) {
    float la = a - __uint_as_float(__float_as_uint(a) & 0xFFFF0000u);
    float lb = b - __uint_as_float(__float_as_uint(b) & 0xFFFF0000u);
    unsigned r;
    asm("cvt.rn.bf16x2.f32 %0, %1, %2;" : "=r"(r) : "f"(lb), "f"(la));
    return r;
}

// ---------------- main kernel ----------------
__global__ __launch_bounds__(256)
void main_kernel(const float* __restrict__ f, const float* __restrict__ Sg) {
    extern __shared__ char smem[];
    const unsigned sb = smem_u32(smem);
    float* Upart = (float*)(smem + ZOFF);

    const int tid  = threadIdx.x;
    const int wid  = tid >> 5;
    const int lane = tid & 31;
    const int b0   = blockIdx.y * 128;
    const int c0   = blockIdx.x * CPS;
    const int c1   = min(c0 + CPS, TOTCH);

    // ---- stage f hi/lo split into SMEM + U partials ----
    {
        const int b = tid >> 1, half = tid & 1;
        const float* fr = f + (size_t)(b0 + b) * NL + half * 32;
        char* frow = smem + b * 272;
        float u = 0.f;
        #pragma unroll
        for (int j = 0; j < 8; j++) {
            float4 v = *(const float4*)(fr + 4 * j);
            u += fmaxf(v.x, 0.f) + fmaxf(v.y, 0.f) + fmaxf(v.z, 0.f) + fmaxf(v.w, 0.f);
            int ch = half * 32 + 4 * j;
            *(uint2*)(frow + ch * 2) =
                make_uint2(packhi(v.x, v.y), packhi(v.z, v.w));
            *(uint2*)(frow + (64 + ch) * 2) =
                make_uint2(packlo(v.x, v.y), packlo(v.z, v.w));
        }
        Upart[half * 128 + b] = u;
    }
    __syncthreads();

    // ---- A fragments (f hi: q=0..3, f lo: q=4..7), persistent in registers ----
    unsigned fa[8][4];
    const int r0 = wid * 16;
    {
        const unsigned laneA = (lane % 16) * 272 + (lane >> 4) * 16;
        #pragma unroll
        for (int q = 0; q < 8; q++)
            ldsm4(fa[q], sb + r0 * 272 + q * 32 + laneA);
    }
    const int rl = r0 + (lane >> 2);
    const float U0 = Upart[rl] + Upart[128 + rl];
    const float U1 = Upart[rl + 8] + Upart[128 + rl + 8];
    __syncthreads();   // f staging dead; buffers may now be written

    // ---- chunk loop ----
    float macc[8][4];
    #pragma unroll
    for (int j = 0; j < 8; j++)
        #pragma unroll
        for (int k = 0; k < 4; k++) macc[j][k] = 0.f;
    float zacc0 = 0.f, zacc1 = 0.f;

    const int srow  = tid >> 2;
    const int ibase = (tid & 3) << 4;
    const float* sp = Sg + ((size_t)c0 * 64 + srow) * NL + ibase;
    float4 v0 = *(const float4*)(sp);
    float4 v1 = *(const float4*)(sp + 4);
    float4 v2 = *(const float4*)(sp + 8);
    float4 v3 = *(const float4*)(sp + 12);

    const unsigned laneB = (lane & 7) * 144 + (lane >> 3) * 16;

    for (int c = c0; c < c1; c++) {
        const int buf = c & 1;
        // store S tile: ss[s][i] and st[i][s] (bf16, exact for 0/1)
        {
            char* ssb = smem + SSOF(buf) + srow * 144 + ibase * 2;
            *(uint2*)(ssb +  0) = make_uint2(packhi(v0.x, v0.y), packhi(v0.z, v0.w));
            *(uint2*)(ssb +  8) = make_uint2(packhi(v1.x, v1.y), packhi(v1.z, v1.w));
            *(uint2*)(ssb + 16) = make_uint2(packhi(v2.x, v2.y), packhi(v2.z, v2.w));
            *(uint2*)(ssb + 24) = make_uint2(packhi(v3.x, v3.y), packhi(v3.z, v3.w));
            char* stb = smem + STOF(buf) + srow * 2;
            const float* vv = (const float*)&v0;  // v0..v3 contiguous? not guaranteed
            // write 16 transposed halves explicitly
            unsigned short* sptr;
            float vals[16] = {v0.x, v0.y, v0.z, v0.w, v1.x, v1.y, v1.z, v1.w,
                              v2.x, v2.y, v2.z, v2.w, v3.x, v3.y, v3.z, v3.w};
            (void)vv;
            #pragma unroll
            for (int e = 0; e < 16; e++) {
                sptr = (unsigned short*)(stb + (ibase + e) * 144);
                *sptr = (unsigned short)(__float_as_uint(vals[e]) >> 16);
            }
        }
        __syncthreads();

        // prefetch next chunk
        if (c + 1 < c1) {
            const float* np = sp + 4096;
            v0 = *(const float4*)(np);
            v1 = *(const float4*)(np + 4);
            v2 = *(const float4*)(np + 8);
            v3 = *(const float4*)(np + 12);
            sp = np;
        }

        // ---- GEMM1: scores[16 rows][64 s] ----
        float d[8][4];
        #pragma unroll
        for (int j = 0; j < 8; j++)
            #pragma unroll
            for (int k = 0; k < 4; k++) d[j][k] = 0.f;

        const unsigned ssb = sb + SSOF(buf) + laneB;
        #pragma unroll
        for (int j = 0; j < 8; j++) {
            #pragma unroll
            for (int qp = 0; qp < 2; qp++) {
                unsigned bfr[4];
                ldsm4(bfr, ssb + j * 1152 + qp * 64);
                mma16816(d[j], fa[2 * qp],     bfr[0], bfr[1]);
                mma16816(d[j], fa[2 * qp + 1], bfr[2], bfr[3]);
                mma16816(d[j], fa[4 + 2 * qp],     bfr[0], bfr[1]);
                mma16816(d[j], fa[4 + 2 * qp + 1], bfr[2], bfr[3]);
            }
        }

        // ---- epilogue: w = exp(score - U); pack into GEMM2 A-fragments ----
        unsigned wh[4][4], wl[4][4];
        #pragma unroll
        for (int j = 0; j < 8; j++) {
            float e0 = __expf(d[j][0] - U0);
            float e1 = __expf(d[j][1] - U0);
            float e2 = __expf(d[j][2] - U1);
            float e3 = __expf(d[j][3] - U1);
            zacc0 += e0 + e1;
            zacc1 += e2 + e3;
            const int q = j >> 1, bx = (j & 1) * 2;
            wh[q][bx]     = packhi(e0, e1);
            wh[q][bx + 1] = packhi(e2, e3);
            wl[q][bx]     = packlo(e0, e1);
            wl[q][bx + 1] = packlo(e2, e3);
        }

        // ---- GEMM2: M[16 rows][64 i] += w . S ----
        const unsigned stb = sb + STOF(buf) + laneB;
        #pragma unroll
        for (int j = 0; j < 8; j++) {
            #pragma unroll
            for (int qp = 0; qp < 2; qp++) {
                unsigned bfr[4];
                ldsm4(bfr, stb + j * 1152 + qp * 64);
                mma16816(macc[j], wh[2 * qp],     bfr[0], bfr[1]);
                mma16816(macc[j], wh[2 * qp + 1], bfr[2], bfr[3]);
                mma16816(macc[j], wl[2 * qp],     bfr[0], bfr[1]);
                mma16816(macc[j], wl[2 * qp + 1], bfr[2], bfr[3]);
            }
        }
    }

    // ---- Z partials (quad reduce) ----
    zacc0 += __shfl_xor_sync(0xFFFFFFFFu, zacc0, 1);
    zacc0 += __shfl_xor_sync(0xFFFFFFFFu, zacc0, 2);
    zacc1 += __shfl_xor_sync(0xFFFFFFFFu, zacc1, 1);
    zacc1 += __shfl_xor_sync(0xFFFFFFFFu, zacc1, 2);
    if ((lane & 3) == 0) {
        const int r = b0 + r0 + (lane >> 2);
        g_Zpart[blockIdx.x * NB + r]     = zacc0;
        g_Zpart[blockIdx.x * NB + r + 8] = zacc1;
    }

    // ---- M partials writeback ----
    {
        float* mb = g_Mpart + (size_t)blockIdx.x * (NB * NL)
                  + (size_t)(b0 + r0 + (lane >> 2)) * NL + (lane & 3) * 2;
        float* mb2 = mb + 8 * NL;
        #pragma unroll
        for (int j = 0; j < 8; j++) {
            *(float2*)(mb  + 8 * j) = make_float2(macc[j][0], macc[j][1]);
            *(float2*)(mb2 + 8 * j) = make_float2(macc[j][2], macc[j][3]);
        }
    }
}

// ---------------- finalize: sum splits, pMargin, BCE partials ----------------
__global__ void finalize_kernel(const float* __restrict__ y,
                                const float* __restrict__ mask,
                                float* __restrict__ out) {
    const int half = threadIdx.x >> 7;
    const int el   = threadIdx.x & 127;
    const int idx  = blockIdx.x * 128 + el;

    float m = 0.f;
    const int kbase = half ? 19 : 0;
    const int kn    = half ? 18 : 19;
    #pragma unroll
    for (int k = 0; k < 19; k++)
        if (k < kn) m += g_Mpart[(size_t)(kbase + k) * (NB * NL) + idx];

    __shared__ float buf[128];
    __shared__ float red[256];
    __shared__ float Zsm[2];
    if (threadIdx.x < 2) {
        float z = 0.f;
        #pragma unroll
        for (int k = 0; k < SPLITS; k++)
            z += g_Zpart[k * NB + blockIdx.x * 2 + threadIdx.x];
        Zsm[threadIdx.x] = z;
    }
    if (half) buf[el] = m;
    __syncthreads();

    float bce = 0.f;
    if (!half) {
        m += buf[el];
        float p = m / Zsm[el >> 6];
        out[1 + idx] = p;
        float yv = y[idx], mv = mask[idx];
        float lp  = fmaxf(logf(p), -100.f);
        float l1p = fmaxf(logf(fmaxf(1.f - p, 0.f)), -100.f);
        bce = -(yv * lp + (1.f - yv) * l1p) * mv;
    }
    red[threadIdx.x] = bce;
    __syncthreads();
    #pragma unroll
    for (int off = 128; off > 0; off >>= 1) {
        if (threadIdx.x < off) red[threadIdx.x] += red[threadIdx.x + off];
        __syncthreads();
    }
    if (threadIdx.x == 0) g_lpart[blockIdx.x] = red[0];
}

__global__ void loss_kernel(float* __restrict__ out) {
    __shared__ float red[256];
    red[threadIdx.x] = g_lpart[threadIdx.x];
    __syncthreads();
    #pragma unroll
    for (int off = 128; off > 0; off >>= 1) {
        if (threadIdx.x < off) red[threadIdx.x] += red[threadIdx.x + off];
        __syncthreads();
    }
    if (threadIdx.x == 0) out[0] = red[0] * (1.f / NB);
}

extern "C" void kernel_launch(void* const* d_in, const int* in_sizes, int n_in,
                              void* d_out, int out_size) {
    const float* f    = (const float*)d_in[0];
    const float* S    = (const float*)d_in[1];
    const float* y    = (const float*)d_in[2];
    const float* mask = (const float*)d_in[3];
    float* out = (float*)d_out;

    dim3 grid(SPLITS, 4);
    main_kernel<<<grid, 256, SMEM_BYTES>>>(f, S);
    finalize_kernel<<<NB * NL / 128, 256>>>(y, mask, out);
    loss_kernel<<<1, 256>>>(out);
}

// round 4
// speedup vs baseline: 4.5642x; 1.0452x over previous
#include <cuda_runtime.h>

// ---------------------------------------------------------------------------
// pLoss via mma.sync (bf16 HMMA): pot = S f^T ; P = softmax_s ; pMargin = P^T S.
// Single-pass softmax with U_b = sum_i max(f,0) shift (S binary => pot <= U).
// f and w are exact hi/lo bf16 splits; S is {0,1} (exact bf16).
// 296 CTAs (74 state-splits x 4 batch-tiles of 128) = 2 CTAs/SM, one wave.
// GEMM2 B-fragments via ldmatrix.trans on the SAME row-major S tile (no S^T copy).
// ---------------------------------------------------------------------------

#define NB       512
#define NL       64
#define SPLITS   74
#define CPS      7           // chunks per split (73*7 + 1 = 512)
#define TOTCH    512         // 512 * 64 = 32768 states exactly

// SMEM (bytes): 2 S tile buffers, each 64 rows x 144B = 9216
#define SSOF(b)  ((b) * 9216)
#define ZOFF     34816       // Upart[2][128] floats (after f staging region)
#define SMEM_BYTES 35840
// f staging (pre-loop only, overlaps tile buffers): 128 rows x 272B = 34816

__device__ float g_Zpart[SPLITS * NB];
__device__ float g_Mpart[SPLITS * NB * NL];
__device__ float g_lpart[256];

// ---------------- helpers ----------------
__device__ __forceinline__ unsigned smem_u32(const void* p) {
    unsigned a;
    asm("{ .reg .u64 t; cvta.to.shared.u64 t, %1; cvt.u32.u64 %0, t; }"
        : "=r"(a) : "l"(p));
    return a;
}
__device__ __forceinline__ void ldsm4(unsigned* r, unsigned addr) {
    asm volatile("ldmatrix.sync.aligned.m8n8.x4.shared.b16 {%0,%1,%2,%3}, [%4];"
                 : "=r"(r[0]), "=r"(r[1]), "=r"(r[2]), "=r"(r[3]) : "r"(addr));
}
__device__ __forceinline__ void ldsm4t(unsigned* r, unsigned addr) {
    asm volatile("ldmatrix.sync.aligned.m8n8.x4.trans.shared.b16 {%0,%1,%2,%3}, [%4];"
                 : "=r"(r[0]), "=r"(r[1]), "=r"(r[2]), "=r"(r[3]) : "r"(addr));
}
__device__ __forceinline__ void mma16816(float* d, const unsigned* a,
                                         unsigned b0, unsigned b1) {
    asm volatile(
        "mma.sync.aligned.m16n8k16.row.col.f32.bf16.bf16.f32 "
        "{%0,%1,%2,%3}, {%4,%5,%6,%7}, {%8,%9}, {%0,%1,%2,%3};"
        : "+f"(d[0]), "+f"(d[1]), "+f"(d[2]), "+f"(d[3])
        : "r"(a[0]), "r"(a[1]), "r"(a[2]), "r"(a[3]), "r"(b0), "r"(b1));
}
__device__ __forceinline__ unsigned packhi(float a, float b) {
    return __byte_perm(__float_as_uint(a), __float_as_uint(b), 0x7632);
}
__device__ __forceinline__ unsigned packlo(float a, float b) {
    float la = a - __uint_as_float(__float_as_uint(a) & 0xFFFF0000u);
    float lb = b - __uint_as_float(__float_as_uint(b) & 0xFFFF0000u);
    unsigned r;
    asm("cvt.rn.bf16x2.f32 %0, %1, %2;" : "=r"(r) : "f"(lb), "f"(la));
    return r;
}

// ---------------- main kernel ----------------
__global__ __launch_bounds__(256, 2)
void main_kernel(const float* __restrict__ f, const float* __restrict__ Sg) {
    extern __shared__ char smem[];
    const unsigned sb = smem_u32(smem);
    float* Upart = (float*)(smem + ZOFF);

    const int tid  = threadIdx.x;
    const int wid  = tid >> 5;
    const int lane = tid & 31;
    const int b0   = blockIdx.y * 128;
    const int c0   = blockIdx.x * CPS;
    const int c1   = min(c0 + CPS, TOTCH);

    // ---- stage f hi/lo split into SMEM + U partials ----
    {
        const int b = tid >> 1, half = tid & 1;
        const float* fr = f + (size_t)(b0 + b) * NL + half * 32;
        char* frow = smem + b * 272;
        float u = 0.f;
        #pragma unroll
        for (int j = 0; j < 8; j++) {
            float4 v = *(const float4*)(fr + 4 * j);
            u += fmaxf(v.x, 0.f) + fmaxf(v.y, 0.f) + fmaxf(v.z, 0.f) + fmaxf(v.w, 0.f);
            int ch = half * 32 + 4 * j;
            *(uint2*)(frow + ch * 2) =
                make_uint2(packhi(v.x, v.y), packhi(v.z, v.w));
            *(uint2*)(frow + (64 + ch) * 2) =
                make_uint2(packlo(v.x, v.y), packlo(v.z, v.w));
        }
        Upart[half * 128 + b] = u;
    }
    __syncthreads();

    // ---- A fragments (f hi: q=0..3, f lo: q=4..7), persistent in registers ----
    unsigned fa[8][4];
    const int r0 = wid * 16;
    {
        const unsigned laneA = (lane % 16) * 272 + (lane >> 4) * 16;
        #pragma unroll
        for (int q = 0; q < 8; q++)
            ldsm4(fa[q], sb + r0 * 272 + q * 32 + laneA);
    }
    const int rl = r0 + (lane >> 2);
    const float U0 = Upart[rl] + Upart[128 + rl];
    const float U1 = Upart[rl + 8] + Upart[128 + rl + 8];
    __syncthreads();   // f staging dead; tile buffers may now be written

    // ---- chunk loop ----
    float macc[8][4];
    #pragma unroll
    for (int j = 0; j < 8; j++)
        #pragma unroll
        for (int k = 0; k < 4; k++) macc[j][k] = 0.f;
    float zacc0 = 0.f, zacc1 = 0.f;

    const int srow  = tid >> 2;
    const int ibase = (tid & 3) << 4;
    const float* sp = Sg + ((size_t)c0 * 64 + srow) * NL + ibase;
    float4 v0 = *(const float4*)(sp);
    float4 v1 = *(const float4*)(sp + 4);
    float4 v2 = *(const float4*)(sp + 8);
    float4 v3 = *(const float4*)(sp + 12);

    const unsigned laneB = (lane & 7) * 144 + (lane >> 3) * 16;  // GEMM1 (non-trans)
    const unsigned laneT = lane * 144;                           // GEMM2 (trans)

    for (int c = c0; c < c1; c++) {
        const int buf = c & 1;
        // store S tile: ss[s][i] bf16 (exact for 0/1)
        {
            char* ssb = smem + SSOF(buf) + srow * 144 + ibase * 2;
            *(uint2*)(ssb +  0) = make_uint2(packhi(v0.x, v0.y), packhi(v0.z, v0.w));
            *(uint2*)(ssb +  8) = make_uint2(packhi(v1.x, v1.y), packhi(v1.z, v1.w));
            *(uint2*)(ssb + 16) = make_uint2(packhi(v2.x, v2.y), packhi(v2.z, v2.w));
            *(uint2*)(ssb + 24) = make_uint2(packhi(v3.x, v3.y), packhi(v3.z, v3.w));
        }
        __syncthreads();

        // prefetch next chunk
        if (c + 1 < c1) {
            const float* np = sp + 4096;
            v0 = *(const float4*)(np);
            v1 = *(const float4*)(np + 4);
            v2 = *(const float4*)(np + 8);
            v3 = *(const float4*)(np + 12);
            sp = np;
        }

        // ---- GEMM1: scores[16 rows][64 s] = f . S^T ----
        float d[8][4];
        #pragma unroll
        for (int j = 0; j < 8; j++)
            #pragma unroll
            for (int k = 0; k < 4; k++) d[j][k] = 0.f;

        const unsigned ssb = sb + SSOF(buf) + laneB;
        #pragma unroll
        for (int j = 0; j < 8; j++) {
            #pragma unroll
            for (int qp = 0; qp < 2; qp++) {
                unsigned bfr[4];
                ldsm4(bfr, ssb + j * 1152 + qp * 64);
                mma16816(d[j], fa[2 * qp],     bfr[0], bfr[1]);
                mma16816(d[j], fa[2 * qp + 1], bfr[2], bfr[3]);
                mma16816(d[j], fa[4 + 2 * qp],     bfr[0], bfr[1]);
                mma16816(d[j], fa[4 + 2 * qp + 1], bfr[2], bfr[3]);
            }
        }

        // ---- epilogue: w = exp(score - U); pack into GEMM2 A-fragments ----
        unsigned wh[4][4], wl[4][4];
        #pragma unroll
        for (int j = 0; j < 8; j++) {
            float e0 = __expf(d[j][0] - U0);
            float e1 = __expf(d[j][1] - U0);
            float e2 = __expf(d[j][2] - U1);
            float e3 = __expf(d[j][3] - U1);
            zacc0 += e0 + e1;
            zacc1 += e2 + e3;
            const int q = j >> 1, bx = (j & 1) * 2;
            wh[q][bx]     = packhi(e0, e1);
            wh[q][bx + 1] = packhi(e2, e3);
            wl[q][bx]     = packlo(e0, e1);
            wl[q][bx + 1] = packlo(e2, e3);
        }

        // ---- GEMM2: M[16 rows][64 i] += w . S  (B via ldmatrix.trans on ss) ----
        const unsigned sst = sb + SSOF(buf) + laneT;
        #pragma unroll
        for (int j = 0; j < 8; j++) {
            #pragma unroll
            for (int qp = 0; qp < 2; qp++) {
                unsigned bfr[4];
                ldsm4t(bfr, sst + qp * 4608 + j * 16);
                mma16816(macc[j], wh[2 * qp],     bfr[0], bfr[1]);
                mma16816(macc[j], wh[2 * qp + 1], bfr[2], bfr[3]);
                mma16816(macc[j], wl[2 * qp],     bfr[0], bfr[1]);
                mma16816(macc[j], wl[2 * qp + 1], bfr[2], bfr[3]);
            }
        }
    }

    // ---- Z partials (quad reduce) ----
    zacc0 += __shfl_xor_sync(0xFFFFFFFFu, zacc0, 1);
    zacc0 += __shfl_xor_sync(0xFFFFFFFFu, zacc0, 2);
    zacc1 += __shfl_xor_sync(0xFFFFFFFFu, zacc1, 1);
    zacc1 += __shfl_xor_sync(0xFFFFFFFFu, zacc1, 2);
    if ((lane & 3) == 0) {
        const int r = b0 + r0 + (lane >> 2);
        g_Zpart[blockIdx.x * NB + r]     = zacc0;
        g_Zpart[blockIdx.x * NB + r + 8] = zacc1;
    }

    // ---- M partials writeback ----
    {
        float* mb = g_Mpart + (size_t)blockIdx.x * (NB * NL)
                  + (size_t)(b0 + r0 + (lane >> 2)) * NL + (lane & 3) * 2;
        float* mb2 = mb + 8 * NL;
        #pragma unroll
        for (int j = 0; j < 8; j++) {
            *(float2*)(mb  + 8 * j) = make_float2(macc[j][0], macc[j][1]);
            *(float2*)(mb2 + 8 * j) = make_float2(macc[j][2], macc[j][3]);
        }
    }
}

// ---------------- finalize: sum splits, pMargin, BCE partials ----------------
__global__ void finalize_kernel(const float* __restrict__ y,
                                const float* __restrict__ mask,
                                float* __restrict__ out) {
    const int half = threadIdx.x >> 7;
    const int el   = threadIdx.x & 127;
    const int idx  = blockIdx.x * 128 + el;

    float m = 0.f;
    const int kbase = half * 37;
    #pragma unroll
    for (int k = 0; k < 37; k++)
        m += g_Mpart[(size_t)(kbase + k) * (NB * NL) + idx];

    __shared__ float buf[128];
    __shared__ float red[256];
    __shared__ float Zsm[2];
    if (threadIdx.x < 2) {
        float z = 0.f;
        #pragma unroll
        for (int k = 0; k < SPLITS; k++)
            z += g_Zpart[k * NB + blockIdx.x * 2 + threadIdx.x];
        Zsm[threadIdx.x] = z;
    }
    if (half) buf[el] = m;
    __syncthreads();

    float bce = 0.f;
    if (!half) {
        m += buf[el];
        float p = m / Zsm[el >> 6];
        out[1 + idx] = p;
        float yv = y[idx], mv = mask[idx];
        float lp  = fmaxf(logf(p), -100.f);
        float l1p = fmaxf(logf(fmaxf(1.f - p, 0.f)), -100.f);
        bce = -(yv * lp + (1.f - yv) * l1p) * mv;
    }
    red[threadIdx.x] = bce;
    __syncthreads();
    #pragma unroll
    for (int off = 128; off > 0; off >>= 1) {
        if (threadIdx.x < off) red[threadIdx.x] += red[threadIdx.x + off];
        __syncthreads();
    }
    if (threadIdx.x == 0) g_lpart[blockIdx.x] = red[0];
}

__global__ void loss_kernel(float* __restrict__ out) {
    __shared__ float red[256];
    red[threadIdx.x] = g_lpart[threadIdx.x];
    __syncthreads();
    #pragma unroll
    for (int off = 128; off > 0; off >>= 1) {
        if (threadIdx.x < off) red[threadIdx.x] += red[threadIdx.x + off];
        __syncthreads();
    }
    if (threadIdx.x == 0) out[0] = red[0] * (1.f / NB);
}

extern "C" void kernel_launch(void* const* d_in, const int* in_sizes, int n_in,
                              void* d_out, int out_size) {
    const float* f    = (const float*)d_in[0];
    const float* S    = (const float*)d_in[1];
    const float* y    = (const float*)d_in[2];
    const float* mask = (const float*)d_in[3];
    float* out = (float*)d_out;

    dim3 grid(SPLITS, 4);
    main_kernel<<<grid, 256, SMEM_BYTES>>>(f, S);
    finalize_kernel<<<NB * NL / 128, 256>>>(y, mask, out);
    loss_kernel<<<1, 256>>>(out);
}

// round 5
// speedup vs baseline: 5.4797x; 1.2006x over previous
#include <cuda_runtime.h>

// ---------------------------------------------------------------------------
// pLoss via mma.sync (bf16 HMMA): pot = S f^T ; P = softmax_s ; pMargin = P^T S.
// No shift needed: S binary, |pot| <= ~26 => exp(pot) within fp32 range, and a
// uniform per-row shift cannot change relative accuracy.
// f is an exact hi/lo bf16 split (pot exact to fp32 accumulation).
// w is rn-rounded to bf16; Z is summed from the SAME rounded values, so
// pMargin = exact softmax of a 2^-9-perturbed weight vector (errors cancel).
// S pre-converted to bf16 once; main loop uses a 3-stage cp.async pipeline.
// 296 CTAs (74 state-splits x 4 batch-tiles of 128) = 2 CTAs/SM, one wave.
// ---------------------------------------------------------------------------

#define NB       512
#define NL       64
#define SPLITS   74
#define CPS      7           // chunks per split (73*7 + 1 = 512)
#define TOTCH    512

// SMEM: 3 cp.async tile buffers, each 64 rows x 144B = 9216 (27648 total).
// f staging (pre-loop only, overlaps buffers): 128 rows x 272B = 34816.
#define SSOF(b)  ((b) * 9216)
#define SMEM_BYTES 34816

__device__ unsigned short g_Sbf[32768 * 64];   // bf16 copy of S (4 MB)
__device__ float g_Zpart[SPLITS * NB];
__device__ float g_Mpart[SPLITS * NB * NL];
__device__ float g_lpart[256];

// ---------------- helpers ----------------
__device__ __forceinline__ unsigned smem_u32(const void* p) {
    unsigned a;
    asm("{ .reg .u64 t; cvta.to.shared.u64 t, %1; cvt.u32.u64 %0, t; }"
        : "=r"(a) : "l"(p));
    return a;
}
__device__ __forceinline__ void ldsm4(unsigned* r, unsigned addr) {
    asm volatile("ldmatrix.sync.aligned.m8n8.x4.shared.b16 {%0,%1,%2,%3}, [%4];"
                 : "=r"(r[0]), "=r"(r[1]), "=r"(r[2]), "=r"(r[3]) : "r"(addr));
}
__device__ __forceinline__ void ldsm4t(unsigned* r, unsigned addr) {
    asm volatile("ldmatrix.sync.aligned.m8n8.x4.trans.shared.b16 {%0,%1,%2,%3}, [%4];"
                 : "=r"(r[0]), "=r"(r[1]), "=r"(r[2]), "=r"(r[3]) : "r"(addr));
}
__device__ __forceinline__ void mma16816(float* d, const unsigned* a,
                                         unsigned b0, unsigned b1) {
    asm volatile(
        "mma.sync.aligned.m16n8k16.row.col.f32.bf16.bf16.f32 "
        "{%0,%1,%2,%3}, {%4,%5,%6,%7}, {%8,%9}, {%0,%1,%2,%3};"
        : "+f"(d[0]), "+f"(d[1]), "+f"(d[2]), "+f"(d[3])
        : "r"(a[0]), "r"(a[1]), "r"(a[2]), "r"(a[3]), "r"(b0), "r"(b1));
}
__device__ __forceinline__ unsigned packhi(float a, float b) {   // exact trunc
    return __byte_perm(__float_as_uint(a), __float_as_uint(b), 0x7632);
}
__device__ __forceinline__ unsigned packlo(float a, float b) {   // exact residual
    float la = a - __uint_as_float(__float_as_uint(a) & 0xFFFF0000u);
    float lb = b - __uint_as_float(__float_as_uint(b) & 0xFFFF0000u);
    unsigned r;
    asm("cvt.rn.bf16x2.f32 %0, %1, %2;" : "=r"(r) : "f"(lb), "f"(la));
    return r;
}
__device__ __forceinline__ unsigned packrn(float a, float b) {   // rn round
    unsigned r;
    asm("cvt.rn.bf16x2.f32 %0, %1, %2;" : "=r"(r) : "f"(b), "f"(a));
    return r;
}
__device__ __forceinline__ void cpasync16(unsigned saddr, const void* g) {
    asm volatile("cp.async.cg.shared.global [%0], [%1], 16;"
                 :: "r"(saddr), "l"(g));
}
__device__ __forceinline__ void cp_commit() {
    asm volatile("cp.async.commit_group;" ::: "memory");
}
__device__ __forceinline__ void cp_wait1() {
    asm volatile("cp.async.wait_group 1;" ::: "memory");
}

// ---------------- S -> bf16 conversion ----------------
__global__ void conv_kernel(const float* __restrict__ S) {
    const int t = blockIdx.x * 256 + threadIdx.x;     // 0..262143, 8 elems each
    float4 a = ((const float4*)S)[2 * t];
    float4 b = ((const float4*)S)[2 * t + 1];
    uint4 o;
    o.x = packrn(a.x, a.y);  o.y = packrn(a.z, a.w);
    o.z = packrn(b.x, b.y);  o.w = packrn(b.z, b.w);
    ((uint4*)g_Sbf)[t] = o;
}

// ---------------- main kernel ----------------
__global__ __launch_bounds__(256, 2)
void main_kernel(const float* __restrict__ f) {
    extern __shared__ char smem[];
    const unsigned sb = smem_u32(smem);

    const int tid  = threadIdx.x;
    const int wid  = tid >> 5;
    const int lane = tid & 31;
    const int b0   = blockIdx.y * 128;
    const int c0   = blockIdx.x * CPS;
    const int c1   = min(c0 + CPS, TOTCH);

    // ---- stage f hi/lo split into SMEM ----
    {
        const int b = tid >> 1, half = tid & 1;
        const float* fr = f + (size_t)(b0 + b) * NL + half * 32;
        char* frow = smem + b * 272;
        #pragma unroll
        for (int j = 0; j < 8; j++) {
            float4 v = *(const float4*)(fr + 4 * j);
            int ch = half * 32 + 4 * j;
            *(uint2*)(frow + ch * 2) =
                make_uint2(packhi(v.x, v.y), packhi(v.z, v.w));
            *(uint2*)(frow + (64 + ch) * 2) =
                make_uint2(packlo(v.x, v.y), packlo(v.z, v.w));
        }
    }
    __syncthreads();

    // ---- A fragments (f hi: q=0..3, f lo: q=4..7), persistent ----
    unsigned fa[8][4];
    const int r0 = wid * 16;
    {
        const unsigned laneA = (lane % 16) * 272 + (lane >> 4) * 16;
        #pragma unroll
        for (int q = 0; q < 8; q++)
            ldsm4(fa[q], sb + r0 * 272 + q * 32 + laneA);
    }
    __syncthreads();   // staging dead; cp.async buffers may now be written

    // ---- cp.async pipeline prologue ----
    const int q0 = tid, q1 = tid + 256;
    const unsigned so0 = (unsigned)((q0 >> 3) * 144 + (q0 & 7) * 16);
    const unsigned so1 = (unsigned)((q1 >> 3) * 144 + (q1 & 7) * 16);

    #define ISSUE(c, buf)                                                   \
        do {                                                                \
            const char* gb_ = (const char*)g_Sbf + (size_t)(c) * 8192;      \
            cpasync16(sb + SSOF(buf) + so0, gb_ + q0 * 16);                 \
            cpasync16(sb + SSOF(buf) + so1, gb_ + q1 * 16);                 \
        } while (0)

    ISSUE(c0, 0); cp_commit();
    if (c0 + 1 < c1) ISSUE(c0 + 1, 1);
    cp_commit();

    // ---- chunk loop ----
    float macc[8][4];
    #pragma unroll
    for (int j = 0; j < 8; j++)
        #pragma unroll
        for (int k = 0; k < 4; k++) macc[j][k] = 0.f;
    float zacc0 = 0.f, zacc1 = 0.f;

    const unsigned laneB = (lane & 7) * 144 + (lane >> 3) * 16;  // GEMM1
    const unsigned laneT = lane * 144;                           // GEMM2 (trans)

    for (int c = c0; c < c1; c++) {
        const int idx = c - c0;
        const int buf = idx % 3;

        cp_wait1();          // chunk c's group complete (own thread)
        __syncthreads();     // visible to all; all warps done with chunk c-1

        if (c + 2 < c1) ISSUE(c + 2, (idx + 2) % 3);
        cp_commit();         // uniform commit keeps group accounting simple

        // ---- GEMM1: scores[16 rows][64 s] = f . S^T ----
        float d[8][4];
        #pragma unroll
        for (int j = 0; j < 8; j++)
            #pragma unroll
            for (int k = 0; k < 4; k++) d[j][k] = 0.f;

        const unsigned ssb = sb + SSOF(buf) + laneB;
        #pragma unroll
        for (int j = 0; j < 8; j++) {
            #pragma unroll
            for (int qp = 0; qp < 2; qp++) {
                unsigned bfr[4];
                ldsm4(bfr, ssb + j * 1152 + qp * 64);
                mma16816(d[j], fa[2 * qp],     bfr[0], bfr[1]);
                mma16816(d[j], fa[2 * qp + 1], bfr[2], bfr[3]);
                mma16816(d[j], fa[4 + 2 * qp],     bfr[0], bfr[1]);
                mma16816(d[j], fa[4 + 2 * qp + 1], bfr[2], bfr[3]);
            }
        }

        // ---- epilogue: w = rn_bf16(exp(pot)); Z from the rounded values ----
        unsigned wh[4][4];
        #pragma unroll
        for (int j = 0; j < 8; j++) {
            float e0 = __expf(d[j][0]);
            float e1 = __expf(d[j][1]);
            float e2 = __expf(d[j][2]);
            float e3 = __expf(d[j][3]);
            const int q = j >> 1, bx = (j & 1) * 2;
            unsigned p01 = packrn(e0, e1);
            unsigned p23 = packrn(e2, e3);
            wh[q][bx]     = p01;
            wh[q][bx + 1] = p23;
            zacc0 += __uint_as_float(p01 << 16) +
                     __uint_as_float(p01 & 0xFFFF0000u);
            zacc1 += __uint_as_float(p23 << 16) +
                     __uint_as_float(p23 & 0xFFFF0000u);
        }

        // ---- GEMM2: M[16 rows][64 i] += w . S (B via ldmatrix.trans) ----
        const unsigned sst = sb + SSOF(buf) + laneT;
        #pragma unroll
        for (int j = 0; j < 8; j++) {
            #pragma unroll
            for (int qp = 0; qp < 2; qp++) {
                unsigned bfr[4];
                ldsm4t(bfr, sst + qp * 4608 + j * 16);
                mma16816(macc[j], wh[2 * qp],     bfr[0], bfr[1]);
                mma16816(macc[j], wh[2 * qp + 1], bfr[2], bfr[3]);
            }
        }
    }
    #undef ISSUE

    // ---- Z partials (quad reduce) ----
    zacc0 += __shfl_xor_sync(0xFFFFFFFFu, zacc0, 1);
    zacc0 += __shfl_xor_sync(0xFFFFFFFFu, zacc0, 2);
    zacc1 += __shfl_xor_sync(0xFFFFFFFFu, zacc1, 1);
    zacc1 += __shfl_xor_sync(0xFFFFFFFFu, zacc1, 2);
    if ((lane & 3) == 0) {
        const int r = b0 + r0 + (lane >> 2);
        g_Zpart[blockIdx.x * NB + r]     = zacc0;
        g_Zpart[blockIdx.x * NB + r + 8] = zacc1;
    }

    // ---- M partials writeback ----
    {
        float* mb = g_Mpart + (size_t)blockIdx.x * (NB * NL)
                  + (size_t)(b0 + r0 + (lane >> 2)) * NL + (lane & 3) * 2;
        float* mb2 = mb + 8 * NL;
        #pragma unroll
        for (int j = 0; j < 8; j++) {
            *(float2*)(mb  + 8 * j) = make_float2(macc[j][0], macc[j][1]);
            *(float2*)(mb2 + 8 * j) = make_float2(macc[j][2], macc[j][3]);
        }
    }
}

// ---------------- finalize: sum splits, pMargin, BCE partials ----------------
__global__ void finalize_kernel(const float* __restrict__ y,
                                const float* __restrict__ mask,
                                float* __restrict__ out) {
    const int half = threadIdx.x >> 7;
    const int el   = threadIdx.x & 127;
    const int idx  = blockIdx.x * 128 + el;

    float m = 0.f;
    const int kbase = half * 37;
    #pragma unroll
    for (int k = 0; k < 37; k++)
        m += g_Mpart[(size_t)(kbase + k) * (NB * NL) + idx];

    __shared__ float buf[128];
    __shared__ float red[256];
    __shared__ float Zsm[2];
    if (threadIdx.x < 2) {
        float z = 0.f;
        #pragma unroll
        for (int k = 0; k < SPLITS; k++)
            z += g_Zpart[k * NB + blockIdx.x * 2 + threadIdx.x];
        Zsm[threadIdx.x] = z;
    }
    if (half) buf[el] = m;
    __syncthreads();

    float bce = 0.f;
    if (!half) {
        m += buf[el];
        float p = m / Zsm[el >> 6];
        out[1 + idx] = p;
        float yv = y[idx], mv = mask[idx];
        float lp  = fmaxf(logf(p), -100.f);
        float l1p = fmaxf(logf(fmaxf(1.f - p, 0.f)), -100.f);
        bce = -(yv * lp + (1.f - yv) * l1p) * mv;
    }
    red[threadIdx.x] = bce;
    __syncthreads();
    #pragma unroll
    for (int off = 128; off > 0; off >>= 1) {
        if (threadIdx.x < off) red[threadIdx.x] += red[threadIdx.x + off];
        __syncthreads();
    }
    if (threadIdx.x == 0) g_lpart[blockIdx.x] = red[0];
}

__global__ void loss_kernel(float* __restrict__ out) {
    __shared__ float red[256];
    red[threadIdx.x] = g_lpart[threadIdx.x];
    __syncthreads();
    #pragma unroll
    for (int off = 128; off > 0; off >>= 1) {
        if (threadIdx.x < off) red[threadIdx.x] += red[threadIdx.x + off];
        __syncthreads();
    }
    if (threadIdx.x == 0) out[0] = red[0] * (1.f / NB);
}

extern "C" void kernel_launch(void* const* d_in, const int* in_sizes, int n_in,
                              void* d_out, int out_size) {
    const float* f    = (const float*)d_in[0];
    const float* S    = (const float*)d_in[1];
    const float* y    = (const float*)d_in[2];
    const float* mask = (const float*)d_in[3];
    float* out = (float*)d_out;

    conv_kernel<<<1024, 256>>>(S);
    dim3 grid(SPLITS, 4);
    main_kernel<<<grid, 256, SMEM_BYTES>>>(f);
    finalize_kernel<<<NB * NL / 128, 256>>>(y, mask, out);
    loss_kernel<<<1, 256>>>(out);
}